// round 11
// baseline (speedup 1.0000x reference)
#include <cuda_runtime.h>
#include <cuda_bf16.h>

// Problem constants (HawkesIntensityFunction: B=2, N=4096, D=256)
#define BATCH 2
#define NLEN  4096
#define DM    256
#define LOG2E 1.4426950408889634f

#define ROWS_PB 512          // rows per block (2 per thread, 256 threads)
#define TJ      128          // j-tile size (events in smem)
#define RT_CNT  (NLEN / ROWS_PB)             // 8 row tiles per batch
#define JT_CNT  (NLEN / TJ)                  // 32 j tiles per batch
#define BLOCKS_PER_BATCH 144                 // sum_{rt=0..7} (32 - 4*rt)

__device__ __forceinline__ float ex2_approx(float x) {
    float r; asm("ex2.approx.f32 %0, %1;" : "=f"(r) : "f"(x)); return r;
}
__device__ __forceinline__ float sqrt_approx(float x) {
    float r; asm("sqrt.approx.f32 %0, %1;" : "=f"(r) : "f"(x)); return r;
}

// Packed per-event: (x, y, u = -beta*log2e*t, -u)
// Pair term for j>i:  alpha * 2^{u_i} * 2^{ng2*dist_ij - u_j}
__device__ float4 g_packed[BATCH * NLEN];

// ---------------------------------------------------------------------------
// Kernel 1: base intensity + packing.  One warp per row (8192 rows).
// out[row] = mu + exp(dot+b) + alpha*(i+1)   (closed form of the j<=i masked
// entries: triu mask applied BEFORE exp -> each contributes exp(0)*exp(0)=1).
// ---------------------------------------------------------------------------
__global__ __launch_bounds__(256)
void hawkes_setup_kernel(const float* __restrict__ z,
                         const float* __restrict__ t,
                         const float* __restrict__ loc,
                         const float* __restrict__ w,
                         const float* __restrict__ bias,
                         const float* __restrict__ mu,
                         const float* __restrict__ alpha,
                         const float* __restrict__ beta,
                         float* __restrict__ out)
{
    const int lane = threadIdx.x & 31;
    const int g    = blockIdx.x * 8 + (threadIdx.x >> 5);  // row id 0..8191
    const int i    = g & (NLEN - 1);

    const float4* wr = (const float4*)w;
    const float4  w0 = __ldg(wr + lane * 2 + 0);
    const float4  w1 = __ldg(wr + lane * 2 + 1);

    const float4* zr = (const float4*)(z + (size_t)g * DM);
    const float4  a0 = __ldg(zr + lane * 2 + 0);
    const float4  a1 = __ldg(zr + lane * 2 + 1);

    float dotp;
    dotp = a0.x * w0.x;
    dotp = fmaf(a0.y, w0.y, dotp);
    dotp = fmaf(a0.z, w0.z, dotp);
    dotp = fmaf(a0.w, w0.w, dotp);
    dotp = fmaf(a1.x, w1.x, dotp);
    dotp = fmaf(a1.y, w1.y, dotp);
    dotp = fmaf(a1.z, w1.z, dotp);
    dotp = fmaf(a1.w, w1.w, dotp);

    #pragma unroll
    for (int off = 16; off > 0; off >>= 1)
        dotp += __shfl_xor_sync(0xffffffffu, dotp, off);

    if (lane == 0) {
        const float muv = __ldg(mu);
        const float av  = __ldg(alpha);
        const float bv  = __ldg(bias);
        const float nb2 = -__ldg(beta) * LOG2E;

        const float base = ex2_approx((dotp + bv) * LOG2E);
        out[g] = muv + base + av * (float)(i + 1);

        const float2 lv = ((const float2*)loc)[g];
        const float  u  = nb2 * __ldg(t + g);
        g_packed[g] = make_float4(lv.x, lv.y, u, -u);
    }
}

// pair term vs event v for row at (px,py): 2^{ng2*dist - u_j}
__device__ __forceinline__ float pair_term(float px, float py, float ng2,
                                           const float4& v)
{
    const float dx = px - v.x;
    const float dy = py - v.y;
    const float sq = fmaf(dx, dx, dy * dy);
    return ex2_approx(fmaf(ng2, sqrt_approx(sq), v.w));
}

// ---------------------------------------------------------------------------
// Kernel 2: pair excitation, tiled. Block = 256 threads = 512 rows (2/thread),
// j-tile of 128 events in smem -> each LDS serves 2 pairs.
// Grid = 288 uniform blocks: single wave, no tail quantization.
// Interior tiles mask-free; diagonal-band tiles predicate the accumulate.
// ---------------------------------------------------------------------------
__global__ __launch_bounds__(256)
void hawkes_pairs_kernel(const float* __restrict__ alpha,
                         const float* __restrict__ gamma,
                         float* __restrict__ out)
{
    __shared__ float4 tile[TJ];

    // decode (b, rt, jt) from blockIdx.x; jt >= 4*rt (triangular tile set)
    int x = blockIdx.x;
    int b = 0;
    if (x >= BLOCKS_PER_BATCH) { b = 1; x -= BLOCKS_PER_BATCH; }
    int rt = 0;
    #pragma unroll
    for (int k = 0; k < RT_CNT; k++) {
        const int w_k = JT_CNT - 4 * k;      // tiles in row-band k
        if (x >= w_k && rt == k) { x -= w_k; rt = k + 1; }
    }
    const int jt = 4 * rt + x;

    const float av  = __ldg(alpha);
    const float ng2 = -__ldg(gamma) * LOG2E;

    const float4* pk = g_packed + b * NLEN;
    const int tid     = threadIdx.x;
    const int rowbase = rt * ROWS_PB;
    const int jbase   = jt * TJ;

    if (tid < TJ) tile[tid] = __ldg(pk + jbase + tid);
    __syncthreads();

    const int i0 = rowbase + tid;          // row A
    const int i1 = i0 + 256;               // row B
    const float4 p0 = pk[i0];
    const float4 p1 = pk[i1];

    float a00 = 0.0f, a01 = 0.0f;          // row A accumulators
    float a10 = 0.0f, a11 = 0.0f;          // row B accumulators

    if (jbase >= rowbase + ROWS_PB) {
        // interior tile: every j > every i in this block, no masking
        #pragma unroll 4
        for (int jj = 0; jj < TJ; jj += 2) {
            const float4 v0 = tile[jj + 0];
            const float4 v1 = tile[jj + 1];
            a00 += pair_term(p0.x, p0.y, ng2, v0);
            a10 += pair_term(p1.x, p1.y, ng2, v0);
            a01 += pair_term(p0.x, p0.y, ng2, v1);
            a11 += pair_term(p1.x, p1.y, ng2, v1);
        }
    } else {
        // diagonal band: same math, predicated accumulate (j > i strictly)
        #pragma unroll 2
        for (int jj = 0; jj < TJ; jj += 2) {
            const int jg0 = jbase + jj;
            const int jg1 = jg0 + 1;
            const float4 v0 = tile[jj + 0];
            const float4 v1 = tile[jj + 1];
            const float e00 = pair_term(p0.x, p0.y, ng2, v0);
            const float e10 = pair_term(p1.x, p1.y, ng2, v0);
            const float e01 = pair_term(p0.x, p0.y, ng2, v1);
            const float e11 = pair_term(p1.x, p1.y, ng2, v1);
            if (jg0 > i0) a00 += e00;
            if (jg0 > i1) a10 += e10;
            if (jg1 > i0) a01 += e01;
            if (jg1 > i1) a11 += e11;
        }
    }

    const float s0 = ex2_approx(p0.z);     // 2^{u_i0}
    const float s1 = ex2_approx(p1.z);     // 2^{u_i1}
    atomicAdd(out + b * NLEN + i0, av * s0 * (a00 + a01));
    atomicAdd(out + b * NLEN + i1, av * s1 * (a10 + a11));
}

extern "C" void kernel_launch(void* const* d_in, const int* in_sizes, int n_in,
                              void* d_out, int out_size)
{
    const float* z     = (const float*)d_in[0];
    const float* t     = (const float*)d_in[1];
    const float* loc   = (const float*)d_in[2];
    const float* w     = (const float*)d_in[3];
    const float* bias  = (const float*)d_in[4];
    const float* mu    = (const float*)d_in[5];
    const float* alpha = (const float*)d_in[6];
    const float* beta  = (const float*)d_in[7];
    const float* gamma = (const float*)d_in[8];
    float* out = (float*)d_out;

    // Kernel 1: 8192 rows, 1 warp/row -> 1024 blocks of 256
    hawkes_setup_kernel<<<1024, 256>>>(z, t, loc, w, bias, mu, alpha, beta, out);
    // Kernel 2: 2 * 144 uniform triangular tiles, single wave
    hawkes_pairs_kernel<<<2 * BLOCKS_PER_BATCH, 256>>>(alpha, gamma, out);
}